// round 4
// baseline (speedup 1.0000x reference)
#include <cuda_runtime.h>
#include <math.h>

// ---------------------------------------------------------------------------
// PoseConvLSTM: 2 ConvLSTM layers (hc=32, hc=64), 3x3 SAME conv, T=128 steps
// on 64x64 grids, then FC. fp32 with packed fma.rn.f32x2 (sm_103a FFMA2).
// R4: unroll cin loop (weight-LDG latency hiding) + k-split FC.
// ---------------------------------------------------------------------------

#define NPIX 4096
#define TT 128

typedef unsigned long long ull;

// ----- scratch -----
__device__ float g_ys1[TT * 32 * NPIX];
__device__ float g_ys2[TT * 64 * NPIX];
__device__ float g_c1[32 * NPIX];
__device__ float g_c2[64 * NPIX];
__device__ float g_zerobuf[64 * NPIX];
__device__ __align__(16) float g_w1p[32 * 35 * 36];
__device__ __align__(16) float g_w2p[64 * 96 * 36];
__device__ float g_fcpart[64 * TT * 6];

__device__ __forceinline__ float sigmf(float x) {
    return 1.0f / (1.0f + __expf(-x));
}
__device__ __forceinline__ float tanh_f(float x) {
    return 1.0f - 2.0f / (__expf(2.0f * x) + 1.0f);
}

// ----- f32x2 helpers -----
__device__ __forceinline__ ull pack2(float lo, float hi) {
    ull r;
    asm("mov.b64 %0, {%1, %2};" : "=l"(r) : "f"(lo), "f"(hi));
    return r;
}
__device__ __forceinline__ ull dup2(float v) {
    ull r;
    asm("mov.b64 %0, {%1, %1};" : "=l"(r) : "f"(v));
    return r;
}
__device__ __forceinline__ void unpack2(ull p, float& lo, float& hi) {
    asm("mov.b64 {%0, %1}, %2;" : "=f"(lo), "=f"(hi) : "l"(p));
}
__device__ __forceinline__ ull ffma2(ull a, ull b, ull c) {
    ull d;
    asm("fma.rn.f32x2 %0, %1, %2, %3;" : "=l"(d) : "l"(a), "l"(b), "l"(c));
    return d;
}

// ----- merged setup (1 launch): zero states + repack both weight tensors ---
__global__ void setup_kernel(const float* __restrict__ w1,
                             const float* __restrict__ w2,
                             float* __restrict__ w1p, float* __restrict__ w2p,
                             float* __restrict__ c1, float* __restrict__ c2,
                             float* __restrict__ zb) {
    int i = blockIdx.x * blockDim.x + threadIdx.x;
    const int N_C1 = 32 * NPIX;
    const int N_C2 = 64 * NPIX;
    const int N_W1 = 32 * 35 * 36;
    const int N_W2 = 64 * 96 * 36;
    if (i < N_C1) { c1[i] = 0.0f; return; }
    i -= N_C1;
    if (i < N_C2) { c2[i] = 0.0f; return; }
    i -= N_C2;
    if (i < N_C2) { zb[i] = 0.0f; return; }
    i -= N_C2;
    if (i < N_W1) {
        int g = i & 3; int r = i >> 2;
        int t = r % 9; r /= 9;
        int cin = r % 35; int co = r / 35;
        w1p[i] = w1[((g * 32 + co) * 35 + cin) * 9 + t];
        return;
    }
    i -= N_W1;
    if (i < N_W2) {
        int g = i & 3; int r = i >> 2;
        int t = r % 9; r /= 9;
        int cin = r % 96; int co = r / 96;
        w2p[i] = w2[((g * 64 + co) * 96 + cin) * 9 + t];
        return;
    }
}

// ----- fused ConvLSTM step -----
template <int HC, int CIN, int CX, int TW, int TH, int PXT>
__global__ void __launch_bounds__(256, 2) lstm_step(
    const float* __restrict__ xin,
    const float* __restrict__ hprev,
    const float* __restrict__ wp,
    const float* __restrict__ bias,
    float* __restrict__ cst,
    float* __restrict__ hout)
{
    constexpr int SROW = (TW + 2 + 3) & ~3;     // 12 (TW8) / 20 (TW16)
    constexpr int SPLANE = (TH + 2) * SROW;
    constexpr int HWIN = (TH + 2) * (TW + 2);
    constexpr int TILES_X = 64 / TW;

    extern __shared__ float sbuf[];
    const int tid = threadIdx.x;
    const int tile = blockIdx.x;
    const int tx0 = (tile % TILES_X) * TW;
    const int ty0 = (tile / TILES_X) * TH;

    for (int idx = tid; idx < CIN * HWIN; idx += 256) {
        int cin = idx / HWIN;
        int r = idx - cin * HWIN;
        int ly = r / (TW + 2);
        int lx = r - ly * (TW + 2);
        int gy = ty0 + ly - 1;
        int gx = tx0 + lx - 1;
        float v = 0.0f;
        if ((unsigned)gy < 64u && (unsigned)gx < 64u) {
            const float* src = (cin < CX) ? (xin + cin * NPIX)
                                          : (hprev + (cin - CX) * NPIX);
            v = src[gy * 64 + gx];
        }
        sbuf[cin * SPLANE + ly * SROW + lx] = v;
    }
    __syncthreads();

    const int co_l = tid >> 5;
    const int l = tid & 31;
    const int py = l & 7;
    const int pxi = l >> 3;
    const int p0 = pxi * PXT;
    const int co = (blockIdx.y << 3) + co_l;

    ull acc0[4], acc1[4];
    {
        ull b0 = pack2(bias[0 * HC + co], bias[1 * HC + co]);
        ull b1 = pack2(bias[2 * HC + co], bias[3 * HC + co]);
#pragma unroll
        for (int j = 0; j < PXT; ++j) { acc0[j] = b0; acc1[j] = b1; }
    }

    const ulonglong2* __restrict__ wq =
        reinterpret_cast<const ulonglong2*>(wp) + (size_t)co * CIN * 9;
    const float* sbase = sbuf + py * SROW + p0;

    // unroll 2: ptxas front-batches weight LDGs of both iterations -> MLP 18,
    // one exposed L2-latency window per two cin, amortized over 144 FMA2 cyc.
#pragma unroll 2
    for (int cin = 0; cin < CIN; ++cin) {
        const float* sr = sbase + cin * SPLANE;
        const ulonglong2* wc = wq + cin * 9;
        ulonglong2 wt[9];
#pragma unroll
        for (int i = 0; i < 9; ++i) wt[i] = wc[i];

        ull in2[3][6];
#pragma unroll
        for (int ky = 0; ky < 3; ++ky) {
            if (PXT == 4) {
                float4 a = *reinterpret_cast<const float4*>(sr + ky * SROW);
                float4 b = *reinterpret_cast<const float4*>(sr + ky * SROW + 4);
                in2[ky][0] = dup2(a.x); in2[ky][1] = dup2(a.y);
                in2[ky][2] = dup2(a.z); in2[ky][3] = dup2(a.w);
                in2[ky][4] = dup2(b.x); in2[ky][5] = dup2(b.y);
            } else {
                float2 a = *reinterpret_cast<const float2*>(sr + ky * SROW);
                float2 b = *reinterpret_cast<const float2*>(sr + ky * SROW + 2);
                in2[ky][0] = dup2(a.x); in2[ky][1] = dup2(a.y);
                in2[ky][2] = dup2(b.x); in2[ky][3] = dup2(b.y);
            }
        }
#pragma unroll
        for (int ky = 0; ky < 3; ++ky)
#pragma unroll
            for (int kx = 0; kx < 3; ++kx) {
                ulonglong2 w = wt[ky * 3 + kx];
#pragma unroll
                for (int j = 0; j < PXT; ++j) {
                    acc0[j] = ffma2(in2[ky][kx + j], w.x, acc0[j]);
                    acc1[j] = ffma2(in2[ky][kx + j], w.y, acc1[j]);
                }
            }
    }

    const int gy = ty0 + py;
    const int base = co * NPIX + gy * 64 + tx0 + p0;
    float cold[4], cn[4], hv[4];
    if (PXT == 4) {
        float4 cv = *reinterpret_cast<const float4*>(cst + base);
        cold[0] = cv.x; cold[1] = cv.y; cold[2] = cv.z; cold[3] = cv.w;
    } else {
        float2 cv = *reinterpret_cast<const float2*>(cst + base);
        cold[0] = cv.x; cold[1] = cv.y;
    }
#pragma unroll
    for (int j = 0; j < PXT; ++j) {
        float zi, zf, zo, zg;
        unpack2(acc0[j], zi, zf);
        unpack2(acc1[j], zo, zg);
        float ig = sigmf(zi);
        float fg = sigmf(zf);
        float og = sigmf(zo);
        float gg = tanh_f(zg);
        float c = fmaf(fg, cold[j], ig * gg);
        cn[j] = c;
        hv[j] = og * tanh_f(c);
    }
    if (PXT == 4) {
        *reinterpret_cast<float4*>(cst + base) =
            make_float4(cn[0], cn[1], cn[2], cn[3]);
        *reinterpret_cast<float4*>(hout + base) =
            make_float4(hv[0], hv[1], hv[2], hv[3]);
    } else {
        *reinterpret_cast<float2*>(cst + base) = make_float2(cn[0], cn[1]);
        *reinterpret_cast<float2*>(hout + base) = make_float2(hv[0], hv[1]);
    }
}

// ----- FC pass 1: k-chunk partials (fc_w chunk stays L1-hot across all t) --
__global__ void __launch_bounds__(256) fc_part(const float* __restrict__ ys2,
                                               const float* __restrict__ fw,
                                               float* __restrict__ part) {
    __shared__ float red[8][6];
    const int kc = blockIdx.x;          // 64 chunks of 4096
    const int tid = threadIdx.x;
    const int lane = tid & 31;
    const int warp = tid >> 5;
    const int k0 = kc * 4096;
    const int NK = 64 * NPIX;

    for (int t = 0; t < TT; ++t) {
        const float* y = ys2 + (size_t)t * NK + k0;
        float acc[6] = {0.f, 0.f, 0.f, 0.f, 0.f, 0.f};
#pragma unroll 4
        for (int k = tid; k < 4096; k += 256) {
            float v = y[k];
#pragma unroll
            for (int j = 0; j < 6; ++j)
                acc[j] = fmaf(v, fw[(size_t)j * NK + k0 + k], acc[j]);
        }
#pragma unroll
        for (int j = 0; j < 6; ++j) {
#pragma unroll
            for (int off = 16; off > 0; off >>= 1)
                acc[j] += __shfl_xor_sync(0xffffffffu, acc[j], off);
        }
        if (lane < 6) red[warp][lane] = acc[lane];
        __syncthreads();
        if (tid < 6) {
            float s = 0.0f;
#pragma unroll
            for (int w = 0; w < 8; ++w) s += red[w][tid];
            part[(kc * TT + t) * 6 + tid] = s;
        }
        __syncthreads();
    }
}

// ----- FC pass 2: deterministic reduce over k-chunks -----
__global__ void fc_reduce(const float* __restrict__ part,
                          const float* __restrict__ fb,
                          float* __restrict__ out) {
    int i = blockIdx.x * blockDim.x + threadIdx.x;   // 768
    if (i >= TT * 6) return;
    int j = i % 6;
    float s = fb[j];
    for (int kc = 0; kc < 64; ++kc) s += part[kc * TT * 6 + i];
    out[i] = s;
}

// ----- pack final states -----
__global__ void finalize_kernel(const float* __restrict__ ys1,
                                const float* __restrict__ c1,
                                const float* __restrict__ ys2,
                                const float* __restrict__ c2,
                                float* __restrict__ out) {
    int i = blockIdx.x * blockDim.x + threadIdx.x;
    const int N1 = 32 * NPIX;
    const int N2 = 64 * NPIX;
    if (i < N1) {
        out[768 + i] = ys1[(size_t)(TT - 1) * N1 + i];
    } else if (i < 2 * N1) {
        out[768 + i] = c1[i - N1];
    } else if (i < 2 * N1 + N2) {
        out[768 + i] = ys2[(size_t)(TT - 1) * N2 + (i - 2 * N1)];
    } else if (i < 2 * N1 + 2 * N2) {
        out[768 + i] = c2[i - 2 * N1 - N2];
    }
}

extern "C" void kernel_launch(void* const* d_in, const int* in_sizes, int n_in,
                              void* d_out, int out_size) {
    const float* input = (const float*)d_in[0];
    const float* w1    = (const float*)d_in[1];
    const float* b1    = (const float*)d_in[2];
    const float* w2    = (const float*)d_in[3];
    const float* b2    = (const float*)d_in[4];
    const float* fcw   = (const float*)d_in[5];
    const float* fcb   = (const float*)d_in[6];
    float* out = (float*)d_out;

    float *ys1, *ys2, *c1, *c2, *zb, *w1p, *w2p, *fcpart;
    cudaGetSymbolAddress((void**)&ys1, g_ys1);
    cudaGetSymbolAddress((void**)&ys2, g_ys2);
    cudaGetSymbolAddress((void**)&c1, g_c1);
    cudaGetSymbolAddress((void**)&c2, g_c2);
    cudaGetSymbolAddress((void**)&zb, g_zerobuf);
    cudaGetSymbolAddress((void**)&w1p, g_w1p);
    cudaGetSymbolAddress((void**)&w2p, g_w2p);
    cudaGetSymbolAddress((void**)&fcpart, g_fcpart);

    const int sm1 = 35 * 120 * 4;
    const int sm2 = 96 * 200 * 4;
    cudaFuncSetAttribute((const void*)lstm_step<32, 35, 3, 8, 8, 2>,
                         cudaFuncAttributeMaxDynamicSharedMemorySize, sm1);
    cudaFuncSetAttribute((const void*)lstm_step<64, 96, 32, 16, 8, 4>,
                         cudaFuncAttributeMaxDynamicSharedMemorySize, sm2);

    const int NSETUP = 32 * NPIX + 3 * 64 * NPIX + 32 * 35 * 36 + 64 * 96 * 36;
    setup_kernel<<<(NSETUP + 255) / 256, 256>>>(w1, w2, w1p, w2p, c1, c2, zb);

    dim3 blk(256);
    dim3 g1(64, 4);
    dim3 g2(32, 8);

    for (int t = 0; t < TT; ++t) {
        const float* x1 = input + (size_t)t * 3 * NPIX;
        const float* hp1 = (t == 0) ? zb : (ys1 + (size_t)(t - 1) * 32 * NPIX);
        float* ho1 = ys1 + (size_t)t * 32 * NPIX;
        lstm_step<32, 35, 3, 8, 8, 2><<<g1, blk, sm1>>>(x1, hp1, w1p, b1, c1, ho1);

        const float* x2 = ys1 + (size_t)t * 32 * NPIX;
        const float* hp2 = (t == 0) ? zb : (ys2 + (size_t)(t - 1) * 64 * NPIX);
        float* ho2 = ys2 + (size_t)t * 64 * NPIX;
        lstm_step<64, 96, 32, 16, 8, 4><<<g2, blk, sm2>>>(x2, hp2, w2p, b2, c2, ho2);
    }

    fc_part<<<64, 256>>>(ys2, fcw, fcpart);
    fc_reduce<<<3, 256>>>(fcpart, fcb, out);

    const int NFIN = 2 * 32 * NPIX + 2 * 64 * NPIX;
    finalize_kernel<<<(NFIN + 255) / 256, 256>>>(ys1, c1, ys2, c2, out);
}

// round 5
// speedup vs baseline: 1.2825x; 1.2825x over previous
#include <cuda_runtime.h>
#include <math.h>

// ---------------------------------------------------------------------------
// PoseConvLSTM: 2 ConvLSTM layers (hc=32, hc=64), 3x3 SAME conv, T=128 steps
// on 64x64 grids, then FC. fp32 with packed fma.rn.f32x2 (sm_103a FFMA2).
// R5: weights staged in SMEM (uniform broadcast LDS), cin-chunked
// double-buffered pipeline with cp.async weight prefetch for layer 2.
// ---------------------------------------------------------------------------

#define NPIX 4096
#define TT 128

typedef unsigned long long ull;

// ----- scratch -----
__device__ float g_ys1[TT * 32 * NPIX];
__device__ float g_ys2[TT * 64 * NPIX];
__device__ float g_c1[32 * NPIX];
__device__ float g_c2[64 * NPIX];
__device__ float g_zerobuf[64 * NPIX];
__device__ __align__(16) float g_w1p[32 * 35 * 36];
__device__ __align__(16) float g_w2p[64 * 96 * 36];
__device__ float g_fcpart[64 * TT * 6];

__device__ __forceinline__ float sigmf(float x) {
    return 1.0f / (1.0f + __expf(-x));
}
__device__ __forceinline__ float tanh_f(float x) {
    return 1.0f - 2.0f / (__expf(2.0f * x) + 1.0f);
}

// ----- f32x2 helpers -----
__device__ __forceinline__ ull pack2(float lo, float hi) {
    ull r;
    asm("mov.b64 %0, {%1, %2};" : "=l"(r) : "f"(lo), "f"(hi));
    return r;
}
__device__ __forceinline__ ull dup2(float v) {
    ull r;
    asm("mov.b64 %0, {%1, %1};" : "=l"(r) : "f"(v));
    return r;
}
__device__ __forceinline__ void unpack2(ull p, float& lo, float& hi) {
    asm("mov.b64 {%0, %1}, %2;" : "=f"(lo), "=f"(hi) : "l"(p));
}
__device__ __forceinline__ ull ffma2(ull a, ull b, ull c) {
    ull d;
    asm("fma.rn.f32x2 %0, %1, %2, %3;" : "=l"(d) : "l"(a), "l"(b), "l"(c));
    return d;
}
__device__ __forceinline__ unsigned smem_u32(const void* p) {
    return (unsigned)__cvta_generic_to_shared(p);
}
__device__ __forceinline__ void cp16(unsigned s, const void* g) {
    asm volatile("cp.async.cg.shared.global [%0], [%1], 16;"
                 :: "r"(s), "l"(g) : "memory");
}
__device__ __forceinline__ void cp_commit() {
    asm volatile("cp.async.commit_group;" ::: "memory");
}
__device__ __forceinline__ void cp_wait0() {
    asm volatile("cp.async.wait_group 0;" ::: "memory");
}

// ----- merged setup (1 launch) -----
__global__ void setup_kernel(const float* __restrict__ w1,
                             const float* __restrict__ w2,
                             float* __restrict__ w1p, float* __restrict__ w2p,
                             float* __restrict__ c1, float* __restrict__ c2,
                             float* __restrict__ zb) {
    int i = blockIdx.x * blockDim.x + threadIdx.x;
    const int N_C1 = 32 * NPIX;
    const int N_C2 = 64 * NPIX;
    const int N_W1 = 32 * 35 * 36;
    const int N_W2 = 64 * 96 * 36;
    if (i < N_C1) { c1[i] = 0.0f; return; }
    i -= N_C1;
    if (i < N_C2) { c2[i] = 0.0f; return; }
    i -= N_C2;
    if (i < N_C2) { zb[i] = 0.0f; return; }
    i -= N_C2;
    if (i < N_W1) {
        int g = i & 3; int r = i >> 2;
        int t = r % 9; r /= 9;
        int cin = r % 35; int co = r / 35;
        w1p[i] = w1[((g * 32 + co) * 35 + cin) * 9 + t];
        return;
    }
    i -= N_W1;
    if (i < N_W2) {
        int g = i & 3; int r = i >> 2;
        int t = r % 9; r /= 9;
        int cin = r % 96; int co = r / 96;
        w2p[i] = w2[((g * 64 + co) * 96 + cin) * 9 + t];
        return;
    }
}

// ----- fused ConvLSTM step, smem-staged weights -----
// block: 256 thr = 8 co * 32 lanes; lane: py = l&7, pxi = l>>3
// smem per buffer: input [CCH][SPLANE] then weights [co_l][cin_l][36]
template <int HC, int CIN, int CX, int TW, int TH, int PXT, int CCH>
__global__ void __launch_bounds__(256, 2) lstm_step(
    const float* __restrict__ xin,
    const float* __restrict__ hprev,
    const float* __restrict__ wp,     // packed [co][cin][tap][gate]
    const float* __restrict__ bias,
    float* __restrict__ cst,
    float* __restrict__ hout)
{
    constexpr int SROW = (TW + 2 + 3) & ~3;
    constexpr int SPLANE = (TH + 2) * SROW;
    constexpr int HWIN = (TH + 2) * (TW + 2);
    constexpr int TILES_X = 64 / TW;
    constexpr int NCH = CIN / CCH;
    constexpr int IN_FL = CCH * SPLANE;
    constexpr int W_FL = 8 * CCH * 36;
    constexpr int BUFSZ = IN_FL + W_FL;
    constexpr int ICNT = CCH * HWIN;
    constexpr int WCNT4 = W_FL / 4;               // float4 count
    constexpr int IR = (ICNT + 255) / 256;

    extern __shared__ float sbuf[];
    const int tid = threadIdx.x;
    const int tile = blockIdx.x;
    const int tx0 = (tile % TILES_X) * TW;
    const int ty0 = (tile / TILES_X) * TH;
    const int co_l = tid >> 5;
    const int l = tid & 31;
    const int py = l & 7;
    const int pxi = l >> 3;
    const int p0 = pxi * PXT;
    const int co0 = blockIdx.y << 3;
    const int co = co0 + co_l;

    const float4* __restrict__ wsrc = reinterpret_cast<const float4*>(wp);

    // ---- load chunk 0 ----
    {
        for (int idx = tid; idx < ICNT; idx += 256) {
            int cin_l = idx / HWIN;
            int r = idx - cin_l * HWIN;
            int ly = r / (TW + 2);
            int lx = r - ly * (TW + 2);
            int gy = ty0 + ly - 1;
            int gx = tx0 + lx - 1;
            float v = 0.0f;
            if ((unsigned)gy < 64u && (unsigned)gx < 64u) {
                const float* src = (cin_l < CX) ? (xin + cin_l * NPIX)
                                                : (hprev + (cin_l - CX) * NPIX);
                v = src[gy * 64 + gx];
            }
            sbuf[cin_l * SPLANE + ly * SROW + lx] = v;
        }
        for (int d = tid; d < WCNT4; d += 256) {
            int cl_co = d / (CCH * 9);
            int rr = d - cl_co * (CCH * 9);
            const float4* g = wsrc + ((size_t)(co0 + cl_co) * CIN) * 9 + rr;
            cp16(smem_u32(reinterpret_cast<float4*>(sbuf + IN_FL) + d), g);
        }
        cp_commit();
        cp_wait0();
    }
    __syncthreads();

    ull acc0[PXT], acc1[PXT];
    {
        ull b0 = pack2(bias[0 * HC + co], bias[1 * HC + co]);
        ull b1 = pack2(bias[2 * HC + co], bias[3 * HC + co]);
#pragma unroll
        for (int j = 0; j < PXT; ++j) { acc0[j] = b0; acc1[j] = b1; }
    }

    for (int ch = 0; ch < NCH; ++ch) {
        float* buf = sbuf + ((NCH > 1) ? (ch & 1) * BUFSZ : 0);
        float* nbuf = sbuf + ((NCH > 1) ? ((ch + 1) & 1) * BUFSZ : 0);
        const bool pf = (NCH > 1) && (ch + 1 < NCH);

        // prefetch next chunk: weights via cp.async, input into registers
        float ist[IR];
        if (pf) {
            const int cin0n = (ch + 1) * CCH;
#pragma unroll
            for (int r = 0; r < IR; ++r) {
                int idx = tid + r * 256;
                float v = 0.0f;
                if (idx < ICNT) {
                    int cin_l = idx / HWIN;
                    int rr = idx - cin_l * HWIN;
                    int ly = rr / (TW + 2);
                    int lx = rr - ly * (TW + 2);
                    int gy = ty0 + ly - 1;
                    int gx = tx0 + lx - 1;
                    if ((unsigned)gy < 64u && (unsigned)gx < 64u) {
                        int ac = cin0n + cin_l;
                        const float* src = (ac < CX)
                            ? (xin + ac * NPIX)
                            : (hprev + (ac - CX) * NPIX);
                        v = src[gy * 64 + gx];
                    }
                }
                ist[r] = v;
            }
            for (int d = tid; d < WCNT4; d += 256) {
                int cl_co = d / (CCH * 9);
                int rr = d - cl_co * (CCH * 9);
                const float4* g = wsrc +
                    ((size_t)(co0 + cl_co) * CIN + cin0n) * 9 + rr;
                cp16(smem_u32(reinterpret_cast<float4*>(nbuf + IN_FL) + d), g);
            }
            cp_commit();
        }

        // ---- compute on current buffer ----
        const float* wbase = buf + IN_FL + co_l * (CCH * 36);
        const float* sb = buf + py * SROW + p0;
#pragma unroll 1
        for (int cl = 0; cl < CCH; ++cl) {
            const float* sr = sb + cl * SPLANE;
            const ulonglong2* wc =
                reinterpret_cast<const ulonglong2*>(wbase + cl * 36);
            ulonglong2 wt[9];
#pragma unroll
            for (int t9 = 0; t9 < 9; ++t9) wt[t9] = wc[t9];

            ull in2[3][PXT + 2];
#pragma unroll
            for (int ky = 0; ky < 3; ++ky) {
                if (PXT == 4) {
                    float4 a = *reinterpret_cast<const float4*>(sr + ky * SROW);
                    float4 b = *reinterpret_cast<const float4*>(sr + ky * SROW + 4);
                    in2[ky][0] = dup2(a.x); in2[ky][1] = dup2(a.y);
                    in2[ky][2] = dup2(a.z); in2[ky][3] = dup2(a.w);
                    in2[ky][4] = dup2(b.x); in2[ky][5] = dup2(b.y);
                } else {
                    float2 a = *reinterpret_cast<const float2*>(sr + ky * SROW);
                    float2 b = *reinterpret_cast<const float2*>(sr + ky * SROW + 2);
                    in2[ky][0] = dup2(a.x); in2[ky][1] = dup2(a.y);
                    in2[ky][2] = dup2(b.x); in2[ky][3] = dup2(b.y);
                }
            }
#pragma unroll
            for (int ky = 0; ky < 3; ++ky)
#pragma unroll
                for (int kx = 0; kx < 3; ++kx) {
                    ulonglong2 w = wt[ky * 3 + kx];
#pragma unroll
                    for (int j = 0; j < PXT; ++j) {
                        acc0[j] = ffma2(in2[ky][kx + j], w.x, acc0[j]);
                        acc1[j] = ffma2(in2[ky][kx + j], w.y, acc1[j]);
                    }
                }
        }

        if (pf) {
            cp_wait0();
#pragma unroll
            for (int r = 0; r < IR; ++r) {
                int idx = tid + r * 256;
                if (idx < ICNT) {
                    int cin_l = idx / HWIN;
                    int rr = idx - cin_l * HWIN;
                    int ly = rr / (TW + 2);
                    int lx = rr - ly * (TW + 2);
                    nbuf[cin_l * SPLANE + ly * SROW + lx] = ist[r];
                }
            }
        }
        if (NCH > 1) __syncthreads();
    }

    // ---- epilogue ----
    const int gy = ty0 + py;
    const int base = co * NPIX + gy * 64 + tx0 + p0;
    float cold[4], cn[4], hv[4];
    if (PXT == 4) {
        float4 cv = *reinterpret_cast<const float4*>(cst + base);
        cold[0] = cv.x; cold[1] = cv.y; cold[2] = cv.z; cold[3] = cv.w;
    } else {
        float2 cv = *reinterpret_cast<const float2*>(cst + base);
        cold[0] = cv.x; cold[1] = cv.y;
    }
#pragma unroll
    for (int j = 0; j < PXT; ++j) {
        float zi, zf, zo, zg;
        unpack2(acc0[j], zi, zf);
        unpack2(acc1[j], zo, zg);
        float ig = sigmf(zi);
        float fg = sigmf(zf);
        float og = sigmf(zo);
        float gg = tanh_f(zg);
        float c = fmaf(fg, cold[j], ig * gg);
        cn[j] = c;
        hv[j] = og * tanh_f(c);
    }
    if (PXT == 4) {
        *reinterpret_cast<float4*>(cst + base) =
            make_float4(cn[0], cn[1], cn[2], cn[3]);
        *reinterpret_cast<float4*>(hout + base) =
            make_float4(hv[0], hv[1], hv[2], hv[3]);
    } else {
        *reinterpret_cast<float2*>(cst + base) = make_float2(cn[0], cn[1]);
        *reinterpret_cast<float2*>(hout + base) = make_float2(hv[0], hv[1]);
    }
}

// ----- FC pass 1: k-chunk partials -----
__global__ void __launch_bounds__(256) fc_part(const float* __restrict__ ys2,
                                               const float* __restrict__ fw,
                                               float* __restrict__ part) {
    __shared__ float red[8][6];
    const int kc = blockIdx.x;
    const int tid = threadIdx.x;
    const int lane = tid & 31;
    const int warp = tid >> 5;
    const int k0 = kc * 4096;
    const int NK = 64 * NPIX;

    for (int t = 0; t < TT; ++t) {
        const float* y = ys2 + (size_t)t * NK + k0;
        float acc[6] = {0.f, 0.f, 0.f, 0.f, 0.f, 0.f};
#pragma unroll 4
        for (int k = tid; k < 4096; k += 256) {
            float v = y[k];
#pragma unroll
            for (int j = 0; j < 6; ++j)
                acc[j] = fmaf(v, fw[(size_t)j * NK + k0 + k], acc[j]);
        }
#pragma unroll
        for (int j = 0; j < 6; ++j) {
#pragma unroll
            for (int off = 16; off > 0; off >>= 1)
                acc[j] += __shfl_xor_sync(0xffffffffu, acc[j], off);
        }
        if (lane < 6) red[warp][lane] = acc[lane];
        __syncthreads();
        if (tid < 6) {
            float s = 0.0f;
#pragma unroll
            for (int w = 0; w < 8; ++w) s += red[w][tid];
            part[(kc * TT + t) * 6 + tid] = s;
        }
        __syncthreads();
    }
}

// ----- FC pass 2 -----
__global__ void fc_reduce(const float* __restrict__ part,
                          const float* __restrict__ fb,
                          float* __restrict__ out) {
    int i = blockIdx.x * blockDim.x + threadIdx.x;
    if (i >= TT * 6) return;
    int j = i % 6;
    float s = fb[j];
    for (int kc = 0; kc < 64; ++kc) s += part[kc * TT * 6 + i];
    out[i] = s;
}

// ----- pack final states -----
__global__ void finalize_kernel(const float* __restrict__ ys1,
                                const float* __restrict__ c1,
                                const float* __restrict__ ys2,
                                const float* __restrict__ c2,
                                float* __restrict__ out) {
    int i = blockIdx.x * blockDim.x + threadIdx.x;
    const int N1 = 32 * NPIX;
    const int N2 = 64 * NPIX;
    if (i < N1) {
        out[768 + i] = ys1[(size_t)(TT - 1) * N1 + i];
    } else if (i < 2 * N1) {
        out[768 + i] = c1[i - N1];
    } else if (i < 2 * N1 + N2) {
        out[768 + i] = ys2[(size_t)(TT - 1) * N2 + (i - 2 * N1)];
    } else if (i < 2 * N1 + 2 * N2) {
        out[768 + i] = c2[i - 2 * N1 - N2];
    }
}

extern "C" void kernel_launch(void* const* d_in, const int* in_sizes, int n_in,
                              void* d_out, int out_size) {
    const float* input = (const float*)d_in[0];
    const float* w1    = (const float*)d_in[1];
    const float* b1    = (const float*)d_in[2];
    const float* w2    = (const float*)d_in[3];
    const float* b2    = (const float*)d_in[4];
    const float* fcw   = (const float*)d_in[5];
    const float* fcb   = (const float*)d_in[6];
    float* out = (float*)d_out;

    float *ys1, *ys2, *c1, *c2, *zb, *w1p, *w2p, *fcpart;
    cudaGetSymbolAddress((void**)&ys1, g_ys1);
    cudaGetSymbolAddress((void**)&ys2, g_ys2);
    cudaGetSymbolAddress((void**)&c1, g_c1);
    cudaGetSymbolAddress((void**)&c2, g_c2);
    cudaGetSymbolAddress((void**)&zb, g_zerobuf);
    cudaGetSymbolAddress((void**)&w1p, g_w1p);
    cudaGetSymbolAddress((void**)&w2p, g_w2p);
    cudaGetSymbolAddress((void**)&fcpart, g_fcpart);

    // L1: single chunk (CCH=35): smem = (35*120 + 8*35*36)*4 = 57120 B
    // L2: 6 chunks of 16, double buffered: 2*(16*200 + 8*16*36)*4 = 62464 B
    const int sm1 = (35 * 120 + 8 * 35 * 36) * 4;
    const int sm2 = 2 * (16 * 200 + 8 * 16 * 36) * 4;
    cudaFuncSetAttribute((const void*)lstm_step<32, 35, 3, 8, 8, 2, 35>,
                         cudaFuncAttributeMaxDynamicSharedMemorySize, sm1);
    cudaFuncSetAttribute((const void*)lstm_step<64, 96, 32, 16, 8, 4, 16>,
                         cudaFuncAttributeMaxDynamicSharedMemorySize, sm2);

    const int NSETUP = 32 * NPIX + 3 * 64 * NPIX + 32 * 35 * 36 + 64 * 96 * 36;
    setup_kernel<<<(NSETUP + 255) / 256, 256>>>(w1, w2, w1p, w2p, c1, c2, zb);

    dim3 blk(256);
    dim3 g1(64, 4);
    dim3 g2(32, 8);

    for (int t = 0; t < TT; ++t) {
        const float* x1 = input + (size_t)t * 3 * NPIX;
        const float* hp1 = (t == 0) ? zb : (ys1 + (size_t)(t - 1) * 32 * NPIX);
        float* ho1 = ys1 + (size_t)t * 32 * NPIX;
        lstm_step<32, 35, 3, 8, 8, 2, 35><<<g1, blk, sm1>>>(
            x1, hp1, w1p, b1, c1, ho1);

        const float* x2 = ys1 + (size_t)t * 32 * NPIX;
        const float* hp2 = (t == 0) ? zb : (ys2 + (size_t)(t - 1) * 64 * NPIX);
        float* ho2 = ys2 + (size_t)t * 64 * NPIX;
        lstm_step<64, 96, 32, 16, 8, 4, 16><<<g2, blk, sm2>>>(
            x2, hp2, w2p, b2, c2, ho2);
    }

    fc_part<<<64, 256>>>(ys2, fcw, fcpart);
    fc_reduce<<<3, 256>>>(fcpart, fcb, out);

    const int NFIN = 2 * 32 * NPIX + 2 * 64 * NPIX;
    finalize_kernel<<<(NFIN + 255) / 256, 256>>>(ys1, c1, ys2, c2, out);
}